// round 4
// baseline (speedup 1.0000x reference)
#include <cuda_runtime.h>

// Canny pipeline: x -> gauss3x3 -> sobel x/y -> mag=jnp.hypot -> NMS -> thin ->
// global max normalize -> steep sigmoids. Outputs concatenated: mag, thin, res.
// Convs + hypot computed EXACTLY (double internal, f32 products exact in f64),
// rounded to f32 at each tensor materialization point (xs, sx, sy, mag) to
// minimize deviation from the reference's own rounding noise.

#define IMG_H 2048
#define IMG_W 2048
#define TILE 32

__device__ unsigned int g_thin_max_bits;   // float bits; thin >= 0

__global__ void init_max_kernel() { g_thin_max_bits = 0u; }

__device__ __forceinline__ int clampi(int v, int hi) { return min(max(v, 0), hi); }

// (c2*w + c1*(1-w)) <= m on both sides, strict f32 ops, no fma contraction.
// NaN/Inf w -> comparisons false, matching JAX.
__device__ __forceinline__ bool nms_cond(float w, float c1p, float c2p,
                                         float c1m, float c2m, float m) {
    float omw = __fsub_rn(1.0f, w);
    float ip  = __fadd_rn(__fmul_rn(c2p, w), __fmul_rn(c1p, omw));
    float im  = __fadd_rn(__fmul_rn(c2m, w), __fmul_rn(c1m, omw));
    return (ip <= m) && (im <= m);
}

__global__ __launch_bounds__(256)
void canny_stage1(const float* __restrict__ x,
                  const float* __restrict__ wgk,
                  const float* __restrict__ wsk,
                  const float* __restrict__ wtk,
                  float* __restrict__ out_mag,
                  float* __restrict__ out_thin)
{
    __shared__ float sX[38][40];   // x tile, halo 3
    __shared__ float sG[36][40];   // gauss (f32-rounded xs), halo 2
    __shared__ float sM[34][36];   // mag, halo 1
    __shared__ float sSx[32][33];
    __shared__ float sSy[32][33];
    __shared__ float kg[9], ks[9], kt[9];
    __shared__ float warp_max[8];

    const int b  = blockIdx.z;
    const int r0 = blockIdx.y * TILE;
    const int c0 = blockIdx.x * TILE;
    const int tid = threadIdx.y * 32 + threadIdx.x;
    const float* xb = x + (size_t)b * IMG_H * IMG_W;

    if (tid < 9)       kg[tid]      = wgk[tid];
    else if (tid < 18) ks[tid - 9]  = wsk[tid - 9];
    else if (tid < 27) kt[tid - 18] = wtk[tid - 18];

    // ---- load x tile with halo 3, replicate clamp at fetch ----
    for (int i = tid; i < 38 * 38; i += 256) {
        int r = i / 38, c = i % 38;
        int gr = clampi(r0 - 3 + r, IMG_H - 1);
        int gc = clampi(c0 - 3 + c, IMG_W - 1);
        sX[r][c] = xb[(size_t)gr * IMG_W + gc];
    }
    __syncthreads();

    // ---- gaussian (exact in double, round once) into 36x36 (halo 2) ----
    for (int i = tid; i < 36 * 36; i += 256) {
        int r = i / 36, c = i % 36;
        double acc = 0.0;
        #pragma unroll
        for (int a = 0; a < 3; a++)
            #pragma unroll
            for (int e = 0; e < 3; e++)
                acc = fma((double)kg[a * 3 + e], (double)sX[r + a][c + e], acc);
        sG[r][c] = (float)acc;   // materialized xs (f32)
    }
    __syncthreads();

    // ---- sobel (exact in double from f32 xs) + exact hypot into 34x34 ----
    for (int i = tid; i < 34 * 34; i += 256) {
        int r = i / 34, c = i % 34;
        int gr = r0 - 1 + r;
        int gc = c0 - 1 + c;
        int rr[3], cc[3];
        #pragma unroll
        for (int a = 0; a < 3; a++) {
            rr[a] = clampi(gr + a - 1, IMG_H - 1) - (r0 - 2);
            cc[a] = clampi(gc + a - 1, IMG_W - 1) - (c0 - 2);
        }
        double sxd = 0.0, syd = 0.0;
        #pragma unroll
        for (int a = 0; a < 3; a++) {
            #pragma unroll
            for (int e = 0; e < 3; e++) {
                double v = (double)sG[rr[a]][cc[e]];
                sxd = fma((double)ks[a * 3 + e], v, sxd);
                syd = fma((double)kt[a * 3 + e], v, syd);
            }
        }
        float sxf = (float)sxd;            // materialized sobel_x (f32)
        float syf = (float)syd;            // materialized sobel_y (f32)
        // mag = hypot(fl32(sx+eps), fl32(sy+eps)), computed exactly then rounded
        float dxf = __fadd_rn(sxf, 1e-10f);
        float dyf = __fadd_rn(syf, 1e-10f);
        double dx = (double)dxf, dy = (double)dyf;
        float m = (float)sqrt(fma(dx, dx, dy * dy));
        sM[r][c] = m;
        if (r >= 1 && r < 33 && c >= 1 && c < 33) {
            sSx[r - 1][c - 1] = sxf;
            sSy[r - 1][c - 1] = syf;
        }
    }
    __syncthreads();

    // ---- NMS per output pixel + write mag/thin + block max ----
    float tmax = 0.0f;
    #pragma unroll
    for (int kk = 0; kk < 4; kk++) {
        int tr = threadIdx.y + 8 * kk;
        int tc = threadIdx.x;
        int gr = r0 + tr, gc = c0 + tc;

        float m  = sM[tr + 1][tc + 1];
        float sx = sSx[tr][tc];
        float sy = sSy[tr][tc];

        float mm00 = sM[tr    ][tc    ], mm01 = sM[tr    ][tc + 1], mm02 = sM[tr    ][tc + 2];
        float mm10 = sM[tr + 1][tc    ],                             mm12 = sM[tr + 1][tc + 2];
        float mm20 = sM[tr + 2][tc    ], mm21 = sM[tr + 2][tc + 1], mm22 = sM[tr + 2][tc + 2];

        bool interior = (gr >= 1) && (gr <= IMG_H - 2) && (gc >= 1) && (gc <= IMG_W - 2);
        bool eroded = interior && (m > 0.0f);
        float ai = fabsf(sy);   // abs_isobel = |sobel_y|
        float aj = fabsf(sx);   // abs_jsobel = |sobel_x|
        bool is_h = eroded && (ai >= aj);
        bool is_v = eroded && (ai <= aj);
        bool up = sx >= 0.0f, down = sx <= 0.0f;
        bool right = sy >= 0.0f, left = sy <= 0.0f;
        bool pa = (up && right) || (down && left);
        bool pb = (down && right) || (up && left);
        float wh = __fdiv_rn(aj, ai);
        float wv = __fdiv_rn(ai, aj);

        bool lm = false;
        if (pa && is_h) lm = nms_cond(wh, mm21, mm22, mm01, mm00, m);
        if (pa && is_v) lm = nms_cond(wv, mm12, mm22, mm10, mm00, m);
        if (pb && is_v) lm = nms_cond(wv, mm12, mm02, mm10, mm20, m);
        if (pb && is_h) lm = nms_cond(wh, mm01, mm02, mm21, mm20, m);

        float thin = lm ? m : 0.0f;
        size_t gidx = (size_t)b * IMG_H * IMG_W + (size_t)gr * IMG_W + gc;
        out_mag[gidx]  = m;
        out_thin[gidx] = thin;
        tmax = fmaxf(tmax, thin);
    }

    #pragma unroll
    for (int o = 16; o > 0; o >>= 1)
        tmax = fmaxf(tmax, __shfl_xor_sync(0xFFFFFFFFu, tmax, o));
    if ((tid & 31) == 0) warp_max[tid >> 5] = tmax;
    __syncthreads();
    if (tid == 0) {
        float v = warp_max[0];
        #pragma unroll
        for (int i = 1; i < 8; i++) v = fmaxf(v, warp_max[i]);
        atomicMax(&g_thin_max_bits, __float_as_uint(v));
    }
}

__device__ __forceinline__ float sigmoidf_(float z) {
    return __fdiv_rn(1.0f, __fadd_rn(1.0f, expf(-z)));
}

__global__ __launch_bounds__(256)
void canny_stage2(const float* __restrict__ thin_u,
                  float* __restrict__ out_thin,
                  float* __restrict__ out_res,
                  const float* __restrict__ lo_p,
                  const float* __restrict__ hi_p,
                  int n4)
{
    int i = blockIdx.x * blockDim.x + threadIdx.x;
    if (i >= n4) return;
    float M  = __uint_as_float(g_thin_max_bits);
    float lo = lo_p[0];
    float hi = hi_p[0];
    const float alpha = 100000.0f;

    float4 t4 = ((const float4*)thin_u)[i];
    float t[4] = {t4.x, t4.y, t4.z, t4.w};
    float th[4], rs[4];
    #pragma unroll
    for (int k = 0; k < 4; k++) {
        float t_n = __fdiv_rn(t[k], M);
        th[k] = t_n;
        float rstrong = sigmoidf_(__fmul_rn(alpha, __fsub_rn(t_n, hi)));
        float rweak   = __fsub_rn(__fmul_rn(0.5f, sigmoidf_(__fmul_rn(alpha, __fsub_rn(hi, t_n)))),
                                  __fmul_rn(0.5f, sigmoidf_(__fmul_rn(alpha, __fsub_rn(lo, t_n)))));
        rs[k] = __fadd_rn(rweak, rstrong);
    }
    ((float4*)out_thin)[i] = make_float4(th[0], th[1], th[2], th[3]);
    ((float4*)out_res)[i]  = make_float4(rs[0], rs[1], rs[2], rs[3]);
}

extern "C" void kernel_launch(void* const* d_in, const int* in_sizes, int n_in,
                              void* d_out, int out_size)
{
    const float* x   = (const float*)d_in[0];
    const float* wg  = (const float*)d_in[1];
    const float* ws  = (const float*)d_in[2];
    const float* wst = (const float*)d_in[3];
    const float* lo  = (const float*)d_in[4];
    const float* hi  = (const float*)d_in[5];

    int total = in_sizes[0];               // B*1*H*W
    int B = total / (IMG_H * IMG_W);

    float* out_mag  = (float*)d_out;
    float* out_thin = out_mag + total;
    float* out_res  = out_thin + total;

    init_max_kernel<<<1, 1>>>();

    dim3 grid(IMG_W / TILE, IMG_H / TILE, B);
    dim3 block(32, 8);
    canny_stage1<<<grid, block>>>(x, wg, ws, wst, out_mag, out_thin);

    int n4 = total / 4;
    canny_stage2<<<(n4 + 255) / 256, 256>>>(out_thin, out_thin, out_res, lo, hi, n4);
}